// round 15
// baseline (speedup 1.0000x reference)
#include <cuda_runtime.h>
#include <math.h>

// ---------------- geometry ----------------
#define IMG_W   512
#define IMG_H   512
#define NCH     96
#define OX      64
#define OY      48
#define INY     58            // OY + 10 halo rows
#define HXM     64            // ulonglong2 (16B) per-row stride (swz(u)<64 for u<64)
#define HXX     64            // float per-row stride: cross field
#define GRID_X  (IMG_W/OX)    // 8
#define GRID_Y  11            // ceil(512/48); last tile covers 32 rows
#define NBLK    (GRID_X*GRID_Y*NCH)   // 8448
#define NTHREADS 384
#define NTASK8  (INY*8)       // 464 8-wide phase-A tasks
#define C2      0.0009f
#define NPIX    25165824.0f

#define SMEM_BYTES (INY*HXM*16 + INY*HXX*4)   // 59392 + 14848 = 74240

typedef unsigned long long ull;

__device__ float    g_blocksums[NBLK];
__device__ unsigned g_count = 0;

__device__ __forceinline__ constexpr float Gw(int k) {
    constexpr float g[11] = {
        0.00102838f, 0.00759878f, 0.03600068f, 0.10936072f, 0.21300538f,
        0.26601175f, 0.21300538f, 0.10936072f, 0.03600068f, 0.00759878f,
        0.00102838f };
    return g[k];
}
__device__ __forceinline__ constexpr float Gz(int k) {
    return (k >= 0 && k < 11) ? Gw(k) : 0.0f;
}

// unit swizzle: conflict-free for BOTH store sweeps and the consecutive-x
// read pattern; maps [0,64) -> [0,64).
__device__ __forceinline__ int swz(int u) { return u ^ ((u >> 3) & 7); }

// -------- f32x2 packed helpers --------
__device__ __forceinline__ constexpr ull pk2c(float lo, float hi) {
    return ((ull)__builtin_bit_cast(unsigned, hi) << 32) |
           (ull)__builtin_bit_cast(unsigned, lo);
}
__device__ __forceinline__ constexpr ull dup2c(float g) { return pk2c(g, g); }
__device__ __forceinline__ constexpr ull GpairC(int k) {
    return pk2c(Gz(k), Gz(k - 1));
}
__device__ __forceinline__ ull pk2(float lo, float hi) {
    ull r; asm("mov.b64 %0, {%1, %2};" : "=l"(r) : "f"(lo), "f"(hi)); return r;
}
__device__ __forceinline__ ull fma2(ull a, ull b, ull c) {
    ull d; asm("fma.rn.f32x2 %0, %1, %2, %3;" : "=l"(d) : "l"(a), "l"(b), "l"(c)); return d;
}
__device__ __forceinline__ ull mul2(ull a, ull b) {
    ull d; asm("mul.rn.f32x2 %0, %1, %2;" : "=l"(d) : "l"(a), "l"(b)); return d;
}
__device__ __forceinline__ ull add2(ull a, ull b) {
    ull d; asm("add.rn.f32x2 %0, %1, %2;" : "=l"(d) : "l"(a), "l"(b)); return d;
}
__device__ __forceinline__ float lo2(ull v) {
    float f; asm("{ .reg .b32 h; mov.b64 {%0, h}, %1; }" : "=f"(f) : "l"(v)); return f;
}
__device__ __forceinline__ float hi2(ull v) {
    float f; asm("{ .reg .b32 l; mov.b64 {l, %0}, %1; }" : "=f"(f) : "l"(v)); return f;
}
__device__ __forceinline__ float rsqrt_approx(float v) {
    float r; asm("rsqrt.approx.f32 %0, %1;" : "=f"(r) : "f"(v)); return r;
}
__device__ __forceinline__ float rcp_approx(float v) {
    float r; asm("rcp.approx.f32 %0, %1;" : "=f"(r) : "f"(v)); return r;
}

extern __shared__ float sm[];

// one f32x2-packed conv step, templated output width
template <int W>
__device__ __forceinline__ void tapsW(
    int v, float a, float b, ull* accM, ull* accS, float* accX)
{
    const ull mp = pk2(a, b);
    const ull sp = mul2(mp, mp);
    const float ab = a * b;
    #pragma unroll
    for (int c = 0; c < W; c++) {
        const int k = v - c;
        if (k >= 0 && k < 11) {
            const ull gg = dup2c(Gw(k));
            accM[c] = fma2(mp, gg, accM[c]);
            accS[c] = fma2(sp, gg, accS[c]);
            accX[c] = fmaf(Gw(k), ab, accX[c]);
        }
    }
}

// ---------- phase A 8-wide task: horizontal 11-tap, 8 output cols ----------
template <bool INTERIOR>
__device__ __forceinline__ void phaseA_task8(
    int t, int tx0, int ty0,
    const float* __restrict__ p1, const float* __restrict__ p2,
    ulonglong2* __restrict__ hMS, float* __restrict__ hX)
{
    const int cg = t & 7;                  // cols [8cg, 8cg+7]
    const int r  = t >> 3;                 // 0..57
    const int gy = ty0 - 5 + r;

    ull  accM[8] = {0,0,0,0,0,0,0,0};
    ull  accS[8] = {0,0,0,0,0,0,0,0};
    float accX[8] = {0,0,0,0,0,0,0,0};

    if (gy >= 0 && gy < IMG_H) {
        const int c0 = tx0 + cg*8;
        if (INTERIOR) {
            // aligned float4 window [c0-8, c0+16): c0 % 8 == 0 always.
            // needed values v = 0..17 (cols c0-5 .. c0+12); v = q*4+s-3.
            const float4* q1 = (const float4*)(p1 + gy*IMG_W + c0 - 8);
            const float4* q2 = (const float4*)(p2 + gy*IMG_W + c0 - 8);
            #pragma unroll
            for (int q = 0; q < 6; q++) {
                const float4 va = __ldg(q1 + q);
                const float4 vb = __ldg(q2 + q);
                const float av[4] = {va.x, va.y, va.z, va.w};
                const float bv[4] = {vb.x, vb.y, vb.z, vb.w};
                #pragma unroll
                for (int s = 0; s < 4; s++) {
                    const int v = q*4 + s - 3;
                    if (v >= 0 && v < 18)
                        tapsW<8>(v, av[s], bv[s], accM, accS, accX);
                }
            }
        } else {
            const float* q1 = p1 + gy*IMG_W + c0 - 5;
            const float* q2 = p2 + gy*IMG_W + c0 - 5;
            #pragma unroll
            for (int v = 0; v < 18; v++) {
                const int gx = c0 - 5 + v;
                const bool ok = (gx >= 0) && (gx < IMG_W);
                const float a = ok ? __ldg(q1 + v) : 0.f;
                const float b = ok ? __ldg(q2 + v) : 0.f;
                tapsW<8>(v, a, b, accM, accS, accX);
            }
        }
    }
    // swizzled stores
    ulonglong2* dst = hMS + r*HXM;
    #pragma unroll
    for (int c = 0; c < 8; c++)
        dst[swz(cg*8 + c)] = make_ulonglong2(accM[c], accS[c]);
    float4* dx = (float4*)(hX + r*HXX + cg*8);
    dx[0] = make_float4(accX[0], accX[1], accX[2], accX[3]);
    dx[1] = make_float4(accX[4], accX[5], accX[6], accX[7]);
}

// ---------- phase A 4-wide task (remainder halves) ----------
template <bool INTERIOR>
__device__ __forceinline__ void phaseA_task4(
    int t, int tx0, int ty0,
    const float* __restrict__ p1, const float* __restrict__ p2,
    ulonglong2* __restrict__ hMS, float* __restrict__ hX)
{
    const int cg = t & 15;                 // cols [4cg, 4cg+3]
    const int r  = t >> 4;                 // 0..57
    const int gy = ty0 - 5 + r;

    ull  accM[4] = {0,0,0,0};
    ull  accS[4] = {0,0,0,0};
    float accX[4] = {0,0,0,0};

    if (gy >= 0 && gy < IMG_H) {
        const int c0 = tx0 + cg*4;
        if (INTERIOR) {
            const float4* q1 = (const float4*)(p1 + gy*IMG_W + c0 - 8);
            const float4* q2 = (const float4*)(p2 + gy*IMG_W + c0 - 8);
            #pragma unroll
            for (int q = 0; q < 5; q++) {
                const float4 va = __ldg(q1 + q);
                const float4 vb = __ldg(q2 + q);
                const float av[4] = {va.x, va.y, va.z, va.w};
                const float bv[4] = {vb.x, vb.y, vb.z, vb.w};
                #pragma unroll
                for (int s = 0; s < 4; s++) {
                    const int v = q*4 + s - 3;
                    if (v >= 0 && v < 14)
                        tapsW<4>(v, av[s], bv[s], accM, accS, accX);
                }
            }
        } else {
            const float* q1 = p1 + gy*IMG_W + c0 - 5;
            const float* q2 = p2 + gy*IMG_W + c0 - 5;
            #pragma unroll
            for (int v = 0; v < 14; v++) {
                const int gx = c0 - 5 + v;
                const bool ok = (gx >= 0) && (gx < IMG_W);
                const float a = ok ? __ldg(q1 + v) : 0.f;
                const float b = ok ? __ldg(q2 + v) : 0.f;
                tapsW<4>(v, a, b, accM, accS, accX);
            }
        }
    }
    ulonglong2* dst = hMS + r*HXM;
    #pragma unroll
    for (int c = 0; c < 4; c++)
        dst[swz(cg*4 + c)] = make_ulonglong2(accM[c], accS[c]);
    *(float4*)(hX + r*HXX + cg*4) = make_float4(accX[0], accX[1], accX[2], accX[3]);
}

__global__ void __launch_bounds__(NTHREADS, 3)
ssim_kernel(const float* __restrict__ img1, const float* __restrict__ img2,
            float* __restrict__ out)
{
    ulonglong2* hMS = (ulonglong2*)sm;               // [INY][HXM] swizzled units
    float*      hX  = sm + (INY*HXM*16)/4;           // [INY][HXX]

    const int tid = threadIdx.x;
    const int tx0 = blockIdx.x * OX;
    const int ty0 = blockIdx.y * OY;
    const int ch  = blockIdx.z;
    const float* p1 = img1 + (size_t)ch * (IMG_W*IMG_H);
    const float* p2 = img2 + (size_t)ch * (IMG_W*IMG_H);

    // ---------- phase A: 384 8-wide tasks + 160 4-wide halves ----------
    const bool interior = (blockIdx.x != 0) && (blockIdx.x != GRID_X-1);
    if (interior) {
        phaseA_task8<true>(tid, tx0, ty0, p1, p2, hMS, hX);
        if (tid < 2*(NTASK8 - NTHREADS)) {     // 160 halves of tasks 384..463
            const int p8 = NTHREADS + (tid >> 1);
            const int t4 = (p8 >> 3)*16 + ((p8 & 7)*2 + (tid & 1));
            phaseA_task4<true>(t4, tx0, ty0, p1, p2, hMS, hX);
        }
    } else {
        phaseA_task8<false>(tid, tx0, ty0, p1, p2, hMS, hX);
        if (tid < 2*(NTASK8 - NTHREADS)) {
            const int p8 = NTHREADS + (tid >> 1);
            const int t4 = (p8 >> 3)*16 + ((p8 & 7)*2 + (tid & 1));
            phaseA_task4<false>(t4, tx0, ty0, p1, p2, hMS, hX);
        }
    }
    __syncthreads();

    // ---------- phase B: vertical 11-tap, 8 rows/thread, two field passes ----------
    float tsum = 0.f;
    {
        const int x   = tid & 63;
        const int yb  = (tid >> 6) * 8;      // group 0..5 -> 8 rows
        const int pxu = swz(x);              // swizzled unit for col x

        // pass 1: M,S fields -> packed partial epilogue (C2 - mu1*mu2, 1/den)
        ull mu12c2[4], rdenp[4];             // row pairs (2p, 2p+1)
        {
            ull accM[8] = {0,0,0,0,0,0,0,0};
            ull accS[8] = {0,0,0,0,0,0,0,0};
            #pragma unroll
            for (int j = 0; j < 18; j++) {
                const ulonglong2 ms = hMS[(yb + j)*HXM + pxu];
                #pragma unroll
                for (int r = 0; r < 8; r++) {
                    const int k = j - r;
                    if (k >= 0 && k < 11) {
                        const ull gg = dup2c(Gw(k));
                        accM[r] = fma2(ms.x, gg, accM[r]);
                        accS[r] = fma2(ms.y, gg, accS[r]);
                    }
                }
            }
            #pragma unroll
            for (int p = 0; p < 4; p++) {
                float m12[2], rd[2];
                #pragma unroll
                for (int h = 0; h < 2; h++) {
                    const int r = 2*p + h;
                    const float mu1 = lo2(accM[r]), mu2 = hi2(accM[r]);
                    const float s11 = lo2(accS[r]) - mu1*mu1;
                    const float s22 = hi2(accS[r]) - mu2*mu2;
                    float v = fabsf(s11) * fabsf(s22);
                    v = fmaxf(v, 1e-30f);
                    const float den = fmaf(v, rsqrt_approx(v), C2); // sqrt(v)+C2
                    rd[h]  = rcp_approx(den);
                    m12[h] = C2 - mu1 * mu2;
                }
                mu12c2[p] = pk2(m12[0], m12[1]);
                rdenp[p]  = pk2(rd[0], rd[1]);
            }
        }

        // pass 2: X field, packed across row pairs with constant weight pairs
        {
            ull accX2[4] = {0,0,0,0};
            #pragma unroll
            for (int j = 0; j < 18; j++) {
                const float vX = hX[(yb + j)*HXX + x];
                const ull vv = pk2(vX, vX);
                #pragma unroll
                for (int p = 0; p < 4; p++) {
                    const int k = j - 2*p;
                    if (k >= 0 && k < 12)
                        accX2[p] = fma2(vv, GpairC(k), accX2[p]);
                }
            }
            // whole-thread validity: last y-tile's invalid rows are full 8-row groups
            if (ty0 + yb < IMG_H) {
                ull acc = 0ull;
                #pragma unroll
                for (int p = 0; p < 4; p++)
                    acc = fma2(add2(accX2[p], mu12c2[p]), rdenp[p], acc);
                tsum = lo2(acc) + hi2(acc);
            }
        }
    }

    // ---------- block reduction ----------
    #pragma unroll
    for (int o = 16; o; o >>= 1) tsum += __shfl_down_sync(0xFFFFFFFFu, tsum, o);
    __shared__ float wsum[12];
    __shared__ bool is_last;
    if ((tid & 31) == 0) wsum[tid >> 5] = tsum;
    __syncthreads();
    if (tid == 0) {
        float s = 0.f;
        #pragma unroll
        for (int i = 0; i < 12; i++) s += wsum[i];
        g_blocksums[(blockIdx.z * GRID_Y + blockIdx.y) * GRID_X + blockIdx.x] = s;
        __threadfence();
        unsigned t = atomicAdd(&g_count, 1u);
        is_last = (t == NBLK - 1);
    }
    __syncthreads();

    // ---------- last CTA: deterministic final reduction ----------
    if (is_last) {
        __threadfence();
        const float4* src = (const float4*)g_blocksums;
        float s = 0.f;
        for (int i = tid; i < NBLK/4; i += NTHREADS) {
            float4 v = src[i];
            s += (v.x + v.y) + (v.z + v.w);
        }
        #pragma unroll
        for (int o = 16; o; o >>= 1) s += __shfl_down_sync(0xFFFFFFFFu, s, o);
        if ((tid & 31) == 0) wsum[tid >> 5] = s;
        __syncthreads();
        if (tid == 0) {
            float tot = 0.f;
            #pragma unroll
            for (int i = 0; i < 12; i++) tot += wsum[i];
            out[0] = tot / NPIX;
            g_count = 0;                      // reset for next replay
        }
    }
}

extern "C" void kernel_launch(void* const* d_in, const int* in_sizes, int n_in,
                              void* d_out, int out_size)
{
    const float* img1 = (const float*)d_in[0];
    const float* img2 = (const float*)d_in[1];
    float* out = (float*)d_out;

    cudaFuncSetAttribute(ssim_kernel,
                         cudaFuncAttributeMaxDynamicSharedMemorySize, SMEM_BYTES);

    dim3 grid(GRID_X, GRID_Y, NCH);
    ssim_kernel<<<grid, NTHREADS, SMEM_BYTES>>>(img1, img2, out);
}

// round 16
// speedup vs baseline: 1.1606x; 1.1606x over previous
#include <cuda_runtime.h>
#include <math.h>

// ---------------- geometry ----------------
#define IMG_W   512
#define IMG_H   512
#define NCH     96
#define OX      64
#define OY      48
#define INY     58            // OY + 10 halo rows
#define HXM     64            // ulonglong2 (16B) per-row stride (swz(u)<64 for u<64)
#define HXX     64            // float per-row stride: cross field
#define GRID_X  (IMG_W/OX)    // 8
#define GRID_Y  11            // ceil(512/48); last tile covers 32 rows
#define NBLK    (GRID_X*GRID_Y*NCH)   // 8448
#define NTHREADS 384
#define NTASKA  (INY*16)      // 928 phase-A tasks (4-wide col groups)
#define C2      0.0009f
#define NPIX    25165824.0f

#define SMEM_BYTES (INY*HXM*16 + INY*HXX*4)   // 59392 + 14848 = 74240

typedef unsigned long long ull;

__device__ float    g_blocksums[NBLK];
__device__ unsigned g_count = 0;

__device__ __forceinline__ constexpr float Gw(int k) {
    constexpr float g[11] = {
        0.00102838f, 0.00759878f, 0.03600068f, 0.10936072f, 0.21300538f,
        0.26601175f, 0.21300538f, 0.10936072f, 0.03600068f, 0.00759878f,
        0.00102838f };
    return g[k];
}

// unit swizzle: conflict-free for BOTH the 16-lane store sweep and the
// consecutive-x read pattern; maps [0,64) -> [0,64).
__device__ __forceinline__ int swz(int u) { return u ^ ((u >> 3) & 7); }

// -------- f32x2 packed helpers --------
__device__ __forceinline__ constexpr ull pk2c(float lo, float hi) {
    return ((ull)__builtin_bit_cast(unsigned, hi) << 32) |
           (ull)__builtin_bit_cast(unsigned, lo);
}
__device__ __forceinline__ constexpr ull dup2c(float g) { return pk2c(g, g); }
__device__ __forceinline__ ull pk2(float lo, float hi) {
    ull r; asm("mov.b64 %0, {%1, %2};" : "=l"(r) : "f"(lo), "f"(hi)); return r;
}
__device__ __forceinline__ ull fma2(ull a, ull b, ull c) {
    ull d; asm("fma.rn.f32x2 %0, %1, %2, %3;" : "=l"(d) : "l"(a), "l"(b), "l"(c)); return d;
}
__device__ __forceinline__ ull mul2(ull a, ull b) {
    ull d; asm("mul.rn.f32x2 %0, %1, %2;" : "=l"(d) : "l"(a), "l"(b)); return d;
}
__device__ __forceinline__ float lo2(ull v) {
    float f; asm("{ .reg .b32 h; mov.b64 {%0, h}, %1; }" : "=f"(f) : "l"(v)); return f;
}
__device__ __forceinline__ float hi2(ull v) {
    float f; asm("{ .reg .b32 l; mov.b64 {l, %0}, %1; }" : "=f"(f) : "l"(v)); return f;
}
__device__ __forceinline__ float rsqrt_approx(float v) {
    float r; asm("rsqrt.approx.f32 %0, %1;" : "=f"(r) : "f"(v)); return r;
}
__device__ __forceinline__ float rcp_approx(float v) {
    float r; asm("rcp.approx.f32 %0, %1;" : "=f"(r) : "f"(v)); return r;
}

extern __shared__ float sm[];

// one f32x2-packed conv step for 4 output columns (register-light)
__device__ __forceinline__ void taps4(
    int v, float a, float b, ull* accM, ull* accS, float* accX)
{
    const ull mp = pk2(a, b);
    const ull sp = mul2(mp, mp);
    const float ab = a * b;
    #pragma unroll
    for (int c = 0; c < 4; c++) {
        const int k = v - c;
        if (k >= 0 && k < 11) {
            const ull gg = dup2c(Gw(k));
            accM[c] = fma2(mp, gg, accM[c]);
            accS[c] = fma2(sp, gg, accS[c]);
            accX[c] = fmaf(Gw(k), ab, accX[c]);
        }
    }
}

// ---------- phase A full task: horizontal 11-tap, 4 output cols ----------
template <bool INTERIOR>
__device__ __forceinline__ void phaseA_task(
    int t, int tx0, int ty0,
    const float* __restrict__ p1, const float* __restrict__ p2,
    ulonglong2* __restrict__ hMS, float* __restrict__ hX)
{
    const int cg = t & 15;                 // cols [4cg, 4cg+3]
    const int r  = t >> 4;                 // 0..57
    const int gy = ty0 - 5 + r;

    ull  accM[4] = {0,0,0,0};
    ull  accS[4] = {0,0,0,0};
    float accX[4] = {0,0,0,0};

    if (gy >= 0 && gy < IMG_H) {
        const int c0 = tx0 + cg*4;
        if (INTERIOR) {
            // aligned float4 window [c0-8, c0+12): c0-8 == 0 (mod 4) always.
            const float4* q1 = (const float4*)(p1 + gy*IMG_W + c0 - 8);
            const float4* q2 = (const float4*)(p2 + gy*IMG_W + c0 - 8);
            #pragma unroll
            for (int q = 0; q < 5; q++) {
                const float4 va = __ldg(q1 + q);
                const float4 vb = __ldg(q2 + q);
                const float av[4] = {va.x, va.y, va.z, va.w};
                const float bv[4] = {vb.x, vb.y, vb.z, vb.w};
                #pragma unroll
                for (int s = 0; s < 4; s++) {
                    const int v = q*4 + s - 3;
                    if (v >= 0 && v < 14)
                        taps4(v, av[s], bv[s], accM, accS, accX);
                }
            }
        } else {
            const float* q1 = p1 + gy*IMG_W + c0 - 5;
            const float* q2 = p2 + gy*IMG_W + c0 - 5;
            #pragma unroll
            for (int v = 0; v < 14; v++) {
                const int gx = c0 - 5 + v;
                const bool ok = (gx >= 0) && (gx < IMG_W);
                const float a = ok ? __ldg(q1 + v) : 0.f;
                const float b = ok ? __ldg(q2 + v) : 0.f;
                taps4(v, a, b, accM, accS, accX);
            }
        }
    }
    // swizzled stores: per STS instruction lanes land on 8 distinct bank-quads
    ulonglong2* dst = hMS + r*HXM;
    #pragma unroll
    for (int c = 0; c < 4; c++)
        dst[swz(cg*4 + c)] = make_ulonglong2(accM[c], accS[c]);
    *(float4*)(hX + r*HXX + cg*4) = make_float4(accX[0], accX[1], accX[2], accX[3]);
}

// ---------- phase A half task: horizontal 11-tap, 2 output cols ----------
__device__ __forceinline__ void phaseA_half(
    int parent, int half, int tx0, int ty0,
    const float* __restrict__ p1, const float* __restrict__ p2,
    ulonglong2* __restrict__ hMS, float* __restrict__ hX)
{
    const int cg = parent & 15;
    const int r  = parent >> 4;
    const int gy = ty0 - 5 + r;
    const int cb = cg*4 + half*2;          // first of 2 output cols (tile-local)

    ull  accM[2] = {0,0};
    ull  accS[2] = {0,0};
    float accX[2] = {0,0};

    if (gy >= 0 && gy < IMG_H) {
        const int c0 = tx0 + cb;
        const float* q1 = p1 + gy*IMG_W + c0 - 5;
        const float* q2 = p2 + gy*IMG_W + c0 - 5;
        #pragma unroll
        for (int v = 0; v < 12; v++) {
            const int gx = c0 - 5 + v;
            const bool ok = (gx >= 0) && (gx < IMG_W);
            const float a = ok ? __ldg(q1 + v) : 0.f;
            const float b = ok ? __ldg(q2 + v) : 0.f;
            const ull mp = pk2(a, b);
            const ull sp = mul2(mp, mp);
            const float ab = a * b;
            #pragma unroll
            for (int c = 0; c < 2; c++) {
                const int k = v - c;
                if (k >= 0 && k < 11) {
                    const ull gg = dup2c(Gw(k));
                    accM[c] = fma2(mp, gg, accM[c]);
                    accS[c] = fma2(sp, gg, accS[c]);
                    accX[c] = fmaf(Gw(k), ab, accX[c]);
                }
            }
        }
    }
    ulonglong2* dst = hMS + r*HXM;
    dst[swz(cb + 0)] = make_ulonglong2(accM[0], accS[0]);
    dst[swz(cb + 1)] = make_ulonglong2(accM[1], accS[1]);
    *(float2*)(hX + r*HXX + cb) = make_float2(accX[0], accX[1]);
}

__global__ void __launch_bounds__(NTHREADS, 3)
ssim_kernel(const float* __restrict__ img1, const float* __restrict__ img2,
            float* __restrict__ out)
{
    ulonglong2* hMS = (ulonglong2*)sm;               // [INY][HXM] swizzled units
    float*      hX  = sm + (INY*HXM*16)/4;           // [INY][HXX]

    const int tid = threadIdx.x;
    const int tx0 = blockIdx.x * OX;
    const int ty0 = blockIdx.y * OY;
    const int ch  = blockIdx.z;
    const float* p1 = img1 + (size_t)ch * (IMG_W*IMG_H);
    const float* p2 = img2 + (size_t)ch * (IMG_W*IMG_H);

    // ---------- phase A: 768 full tasks (2 rounds) + 320 half tasks ----------
    const bool interior = (blockIdx.x != 0) && (blockIdx.x != GRID_X-1);
    if (interior) {
        phaseA_task<true>(tid, tx0, ty0, p1, p2, hMS, hX);
        phaseA_task<true>(tid + NTHREADS, tx0, ty0, p1, p2, hMS, hX);
    } else {
        phaseA_task<false>(tid, tx0, ty0, p1, p2, hMS, hX);
        phaseA_task<false>(tid + NTHREADS, tx0, ty0, p1, p2, hMS, hX);
    }
    if (tid < 2*(NTASKA - 2*NTHREADS)) {   // 320 half tasks
        const int parent = 2*NTHREADS + (tid >> 1);
        phaseA_half(parent, tid & 1, tx0, ty0, p1, p2, hMS, hX);
    }
    __syncthreads();

    // ---------- phase B: vertical 11-tap, 8 rows/thread, two field passes ----------
    float tsum = 0.f;
    {
        const int x   = tid & 63;
        const int yb  = (tid >> 6) * 8;      // group 0..5 -> 8 rows
        const int pxu = swz(x);              // swizzled unit for col x

        // pass 1: M,S fields -> packed partial epilogue (C2 - mu1*mu2, 1/den)
        ull mu12c2[4], rdenp[4];             // row pairs (2p, 2p+1)
        {
            ull accM[8] = {0,0,0,0,0,0,0,0};
            ull accS[8] = {0,0,0,0,0,0,0,0};
            #pragma unroll
            for (int j = 0; j < 18; j++) {
                const ulonglong2 ms = hMS[(yb + j)*HXM + pxu];
                #pragma unroll
                for (int r = 0; r < 8; r++) {
                    const int k = j - r;
                    if (k >= 0 && k < 11) {
                        const ull gg = dup2c(Gw(k));
                        accM[r] = fma2(ms.x, gg, accM[r]);
                        accS[r] = fma2(ms.y, gg, accS[r]);
                    }
                }
            }
            #pragma unroll
            for (int p = 0; p < 4; p++) {
                float m12[2], rd[2];
                #pragma unroll
                for (int h = 0; h < 2; h++) {
                    const int r = 2*p + h;
                    const float mu1 = lo2(accM[r]), mu2 = hi2(accM[r]);
                    const float s11 = lo2(accS[r]) - mu1*mu1;
                    const float s22 = hi2(accS[r]) - mu2*mu2;
                    float v = fabsf(s11) * fabsf(s22);
                    v = fmaxf(v, 1e-30f);
                    const float den = fmaf(v, rsqrt_approx(v), C2); // sqrt(v)+C2
                    rd[h]  = rcp_approx(den);
                    m12[h] = C2 - mu1 * mu2;
                }
                mu12c2[p] = pk2(m12[0], m12[1]);
                rdenp[p]  = pk2(rd[0], rd[1]);
            }
        }

        // pass 2: X field, scalar FFMA-imm conv (rt=1, no pack movs / const regs)
        {
            float accX[8] = {0,0,0,0,0,0,0,0};
            #pragma unroll
            for (int j = 0; j < 18; j++) {
                const float vX = hX[(yb + j)*HXX + x];
                #pragma unroll
                for (int r = 0; r < 8; r++) {
                    const int k = j - r;
                    if (k >= 0 && k < 11)
                        accX[r] = fmaf(Gw(k), vX, accX[r]);
                }
            }
            // whole-thread validity: last y-tile's invalid rows are full 8-row groups
            if (ty0 + yb < IMG_H) {
                #pragma unroll
                for (int p = 0; p < 4; p++) {
                    tsum = fmaf(accX[2*p+0] + lo2(mu12c2[p]), lo2(rdenp[p]), tsum);
                    tsum = fmaf(accX[2*p+1] + hi2(mu12c2[p]), hi2(rdenp[p]), tsum);
                }
            }
        }
    }

    // ---------- block reduction ----------
    #pragma unroll
    for (int o = 16; o; o >>= 1) tsum += __shfl_down_sync(0xFFFFFFFFu, tsum, o);
    __shared__ float wsum[12];
    __shared__ bool is_last;
    if ((tid & 31) == 0) wsum[tid >> 5] = tsum;
    __syncthreads();
    if (tid == 0) {
        float s = 0.f;
        #pragma unroll
        for (int i = 0; i < 12; i++) s += wsum[i];
        g_blocksums[(blockIdx.z * GRID_Y + blockIdx.y) * GRID_X + blockIdx.x] = s;
        __threadfence();
        unsigned t = atomicAdd(&g_count, 1u);
        is_last = (t == NBLK - 1);
    }
    __syncthreads();

    // ---------- last CTA: deterministic final reduction ----------
    if (is_last) {
        __threadfence();
        const float4* src = (const float4*)g_blocksums;
        float s = 0.f;
        for (int i = tid; i < NBLK/4; i += NTHREADS) {
            float4 v = src[i];
            s += (v.x + v.y) + (v.z + v.w);
        }
        #pragma unroll
        for (int o = 16; o; o >>= 1) s += __shfl_down_sync(0xFFFFFFFFu, s, o);
        if ((tid & 31) == 0) wsum[tid >> 5] = s;
        __syncthreads();
        if (tid == 0) {
            float tot = 0.f;
            #pragma unroll
            for (int i = 0; i < 12; i++) tot += wsum[i];
            out[0] = tot / NPIX;
            g_count = 0;                      // reset for next replay
        }
    }
}

extern "C" void kernel_launch(void* const* d_in, const int* in_sizes, int n_in,
                              void* d_out, int out_size)
{
    const float* img1 = (const float*)d_in[0];
    const float* img2 = (const float*)d_in[1];
    float* out = (float*)d_out;

    cudaFuncSetAttribute(ssim_kernel,
                         cudaFuncAttributeMaxDynamicSharedMemorySize, SMEM_BYTES);

    dim3 grid(GRID_X, GRID_Y, NCH);
    ssim_kernel<<<grid, NTHREADS, SMEM_BYTES>>>(img1, img2, out);
}

// round 17
// speedup vs baseline: 1.1843x; 1.0204x over previous
#include <cuda_runtime.h>
#include <math.h>

// ---------------- geometry ----------------
#define IMG_W   512
#define IMG_H   512
#define NCH     96
#define OX      64
#define OY      48
#define INY     58            // OY + 10 halo rows
#define HXM     64            // ulonglong2 (16B) per-row stride (swz(u)<64 for u<64)
#define HXX     64            // float per-row stride: cross field
#define GRID_X  (IMG_W/OX)    // 8
#define GRID_Y  11            // ceil(512/48); last tile covers 32 rows
#define NBLK    (GRID_X*GRID_Y*NCH)   // 8448
#define NTHREADS 384
#define NTASKA  (INY*16)      // 928 phase-A tasks (4-wide col groups)
#define NHALF   (NTASKA - 2*NTHREADS)   // 160 remainder parents
#define C2      0.0009f
#define NPIX    25165824.0f

#define SMEM_BYTES (INY*HXM*16 + INY*HXX*4)   // 59392 + 14848 = 74240

typedef unsigned long long ull;

__device__ float    g_blocksums[NBLK];
__device__ unsigned g_count = 0;

__device__ __forceinline__ constexpr float Gw(int k) {
    constexpr float g[11] = {
        0.00102838f, 0.00759878f, 0.03600068f, 0.10936072f, 0.21300538f,
        0.26601175f, 0.21300538f, 0.10936072f, 0.03600068f, 0.00759878f,
        0.00102838f };
    return g[k];
}

// unit swizzle: conflict-free for BOTH the 16-lane store sweep and the
// consecutive-x read pattern; maps [0,64) -> [0,64).
__device__ __forceinline__ int swz(int u) { return u ^ ((u >> 3) & 7); }

// -------- f32x2 packed helpers --------
__device__ __forceinline__ constexpr ull pk2c(float lo, float hi) {
    return ((ull)__builtin_bit_cast(unsigned, hi) << 32) |
           (ull)__builtin_bit_cast(unsigned, lo);
}
__device__ __forceinline__ constexpr ull dup2c(float g) { return pk2c(g, g); }
__device__ __forceinline__ ull pk2(float lo, float hi) {
    ull r; asm("mov.b64 %0, {%1, %2};" : "=l"(r) : "f"(lo), "f"(hi)); return r;
}
__device__ __forceinline__ ull fma2(ull a, ull b, ull c) {
    ull d; asm("fma.rn.f32x2 %0, %1, %2, %3;" : "=l"(d) : "l"(a), "l"(b), "l"(c)); return d;
}
__device__ __forceinline__ ull mul2(ull a, ull b) {
    ull d; asm("mul.rn.f32x2 %0, %1, %2;" : "=l"(d) : "l"(a), "l"(b)); return d;
}
__device__ __forceinline__ float lo2(ull v) {
    float f; asm("{ .reg .b32 h; mov.b64 {%0, h}, %1; }" : "=f"(f) : "l"(v)); return f;
}
__device__ __forceinline__ float hi2(ull v) {
    float f; asm("{ .reg .b32 l; mov.b64 {l, %0}, %1; }" : "=f"(f) : "l"(v)); return f;
}
__device__ __forceinline__ float sqrt_approx(float v) {
    float r; asm("sqrt.approx.f32 %0, %1;" : "=f"(r) : "f"(v)); return r;
}
__device__ __forceinline__ float rcp_approx(float v) {
    float r; asm("rcp.approx.f32 %0, %1;" : "=f"(r) : "f"(v)); return r;
}

extern __shared__ float sm[];

// one f32x2-packed conv step, templated output width
template <int W>
__device__ __forceinline__ void tapsW(
    int v, float a, float b, ull* accM, ull* accS, float* accX)
{
    const ull mp = pk2(a, b);
    const ull sp = mul2(mp, mp);
    const float ab = a * b;
    #pragma unroll
    for (int c = 0; c < W; c++) {
        const int k = v - c;
        if (k >= 0 && k < 11) {
            const ull gg = dup2c(Gw(k));
            accM[c] = fma2(mp, gg, accM[c]);
            accS[c] = fma2(sp, gg, accS[c]);
            accX[c] = fmaf(Gw(k), ab, accX[c]);
        }
    }
}

// ---------- phase A full task: horizontal 11-tap, 4 output cols ----------
template <bool INTERIOR>
__device__ __forceinline__ void phaseA_task(
    int t, int tx0, int ty0,
    const float* __restrict__ p1, const float* __restrict__ p2,
    ulonglong2* __restrict__ hMS, float* __restrict__ hX)
{
    const int cg = t & 15;                 // cols [4cg, 4cg+3]
    const int r  = t >> 4;                 // 0..57
    const int gy = ty0 - 5 + r;

    ull  accM[4] = {0,0,0,0};
    ull  accS[4] = {0,0,0,0};
    float accX[4] = {0,0,0,0};

    if (gy >= 0 && gy < IMG_H) {
        const int c0 = tx0 + cg*4;
        if (INTERIOR) {
            // aligned float4 window [c0-8, c0+12): c0-8 == 0 (mod 4) always.
            const float4* q1 = (const float4*)(p1 + gy*IMG_W + c0 - 8);
            const float4* q2 = (const float4*)(p2 + gy*IMG_W + c0 - 8);
            #pragma unroll
            for (int q = 0; q < 5; q++) {
                const float4 va = __ldg(q1 + q);
                const float4 vb = __ldg(q2 + q);
                const float av[4] = {va.x, va.y, va.z, va.w};
                const float bv[4] = {vb.x, vb.y, vb.z, vb.w};
                #pragma unroll
                for (int s = 0; s < 4; s++) {
                    const int v = q*4 + s - 3;
                    if (v >= 0 && v < 14)
                        tapsW<4>(v, av[s], bv[s], accM, accS, accX);
                }
            }
        } else {
            const float* q1 = p1 + gy*IMG_W + c0 - 5;
            const float* q2 = p2 + gy*IMG_W + c0 - 5;
            #pragma unroll
            for (int v = 0; v < 14; v++) {
                const int gx = c0 - 5 + v;
                const bool ok = (gx >= 0) && (gx < IMG_W);
                const float a = ok ? __ldg(q1 + v) : 0.f;
                const float b = ok ? __ldg(q2 + v) : 0.f;
                tapsW<4>(v, a, b, accM, accS, accX);
            }
        }
    }
    // swizzled stores: per STS instruction lanes land on 8 distinct bank-quads
    ulonglong2* dst = hMS + r*HXM;
    #pragma unroll
    for (int c = 0; c < 4; c++)
        dst[swz(cg*4 + c)] = make_ulonglong2(accM[c], accS[c]);
    *(float4*)(hX + r*HXX + cg*4) = make_float4(accX[0], accX[1], accX[2], accX[3]);
}

// ---------- phase A half task: horizontal 11-tap, 2 output cols ----------
// HALF is compile-time (warp-uniform dispatch) so the aligned window base
// and all tap indices fold to immediates.
template <bool INTERIOR, int HALF>
__device__ __forceinline__ void phaseA_half(
    int parent, int tx0, int ty0,
    const float* __restrict__ p1, const float* __restrict__ p2,
    ulonglong2* __restrict__ hMS, float* __restrict__ hX)
{
    const int cg = parent & 15;
    const int r  = parent >> 4;
    const int gy = ty0 - 5 + r;
    const int cb = cg*4 + HALF*2;          // first of 2 output cols (tile-local)

    ull  accM[2] = {0,0};
    ull  accS[2] = {0,0};
    float accX[2] = {0,0};

    if (gy >= 0 && gy < IMG_H) {
        const int c0 = tx0 + cb;
        if (INTERIOR) {
            // HALF=0: c0 % 4 == 0 -> window [c0-8,  c0+8),  v = q*4+s-3
            // HALF=1: c0 % 4 == 2 -> window [c0-6,  c0+10), v = q*4+s-1
            // needed v = 0..11 (cols c0-5 .. c0+6)
            const int off = HALF ? 6 : 8;
            const int D   = HALF ? 1 : 3;
            const float4* q1 = (const float4*)(p1 + gy*IMG_W + c0 - off);
            const float4* q2 = (const float4*)(p2 + gy*IMG_W + c0 - off);
            #pragma unroll
            for (int q = 0; q < 4; q++) {
                const float4 va = __ldg(q1 + q);
                const float4 vb = __ldg(q2 + q);
                const float av[4] = {va.x, va.y, va.z, va.w};
                const float bv[4] = {vb.x, vb.y, vb.z, vb.w};
                #pragma unroll
                for (int s = 0; s < 4; s++) {
                    const int v = q*4 + s - D;
                    if (v >= 0 && v < 12)
                        tapsW<2>(v, av[s], bv[s], accM, accS, accX);
                }
            }
        } else {
            const float* q1 = p1 + gy*IMG_W + c0 - 5;
            const float* q2 = p2 + gy*IMG_W + c0 - 5;
            #pragma unroll
            for (int v = 0; v < 12; v++) {
                const int gx = c0 - 5 + v;
                const bool ok = (gx >= 0) && (gx < IMG_W);
                const float a = ok ? __ldg(q1 + v) : 0.f;
                const float b = ok ? __ldg(q2 + v) : 0.f;
                tapsW<2>(v, a, b, accM, accS, accX);
            }
        }
    }
    ulonglong2* dst = hMS + r*HXM;
    dst[swz(cb + 0)] = make_ulonglong2(accM[0], accS[0]);
    dst[swz(cb + 1)] = make_ulonglong2(accM[1], accS[1]);
    *(float2*)(hX + r*HXX + cb) = make_float2(accX[0], accX[1]);
}

__global__ void __launch_bounds__(NTHREADS, 3)
ssim_kernel(const float* __restrict__ img1, const float* __restrict__ img2,
            float* __restrict__ out)
{
    ulonglong2* hMS = (ulonglong2*)sm;               // [INY][HXM] swizzled units
    float*      hX  = sm + (INY*HXM*16)/4;           // [INY][HXX]

    const int tid = threadIdx.x;
    const int tx0 = blockIdx.x * OX;
    const int ty0 = blockIdx.y * OY;
    const int ch  = blockIdx.z;
    const float* p1 = img1 + (size_t)ch * (IMG_W*IMG_H);
    const float* p2 = img2 + (size_t)ch * (IMG_W*IMG_H);

    // ---------- phase A: 768 full tasks (2 rounds) + 320 half tasks ----------
    // Half-task dispatch is warp-uniform in HALF: tid 0..159 -> HALF=0,
    // tid 160..319 -> HALF=1 (warp 5 starts at 160).
    const bool interior = (blockIdx.x != 0) && (blockIdx.x != GRID_X-1);
    if (interior) {
        phaseA_task<true>(tid, tx0, ty0, p1, p2, hMS, hX);
        phaseA_task<true>(tid + NTHREADS, tx0, ty0, p1, p2, hMS, hX);
        if (tid < NHALF)
            phaseA_half<true, 0>(2*NTHREADS + tid, tx0, ty0, p1, p2, hMS, hX);
        else if (tid < 2*NHALF)
            phaseA_half<true, 1>(2*NTHREADS + tid - NHALF, tx0, ty0, p1, p2, hMS, hX);
    } else {
        phaseA_task<false>(tid, tx0, ty0, p1, p2, hMS, hX);
        phaseA_task<false>(tid + NTHREADS, tx0, ty0, p1, p2, hMS, hX);
        if (tid < NHALF)
            phaseA_half<false, 0>(2*NTHREADS + tid, tx0, ty0, p1, p2, hMS, hX);
        else if (tid < 2*NHALF)
            phaseA_half<false, 1>(2*NTHREADS + tid - NHALF, tx0, ty0, p1, p2, hMS, hX);
    }
    __syncthreads();

    // ---------- phase B: vertical 11-tap, 8 rows/thread, two field passes ----------
    float tsum = 0.f;
    {
        const int x   = tid & 63;
        const int yb  = (tid >> 6) * 8;      // group 0..5 -> 8 rows
        const int pxu = swz(x);              // swizzled unit for col x

        // pass 1: M,S fields -> packed partial epilogue (C2 - mu1*mu2, 1/den)
        ull mu12c2[4], rdenp[4];             // row pairs (2p, 2p+1)
        {
            ull accM[8] = {0,0,0,0,0,0,0,0};
            ull accS[8] = {0,0,0,0,0,0,0,0};
            #pragma unroll
            for (int j = 0; j < 18; j++) {
                const ulonglong2 ms = hMS[(yb + j)*HXM + pxu];
                #pragma unroll
                for (int r = 0; r < 8; r++) {
                    const int k = j - r;
                    if (k >= 0 && k < 11) {
                        const ull gg = dup2c(Gw(k));
                        accM[r] = fma2(ms.x, gg, accM[r]);
                        accS[r] = fma2(ms.y, gg, accS[r]);
                    }
                }
            }
            #pragma unroll
            for (int p = 0; p < 4; p++) {
                float m12[2], rd[2];
                #pragma unroll
                for (int h = 0; h < 2; h++) {
                    const int r = 2*p + h;
                    const float mu1 = lo2(accM[r]), mu2 = hi2(accM[r]);
                    const float s11 = lo2(accS[r]) - mu1*mu1;
                    const float s22 = hi2(accS[r]) - mu2*mu2;
                    const float v = fabsf(s11) * fabsf(s22);
                    const float den = sqrt_approx(v) + C2;  // sqrt(0)=0 -> C2
                    rd[h]  = rcp_approx(den);
                    m12[h] = C2 - mu1 * mu2;
                }
                mu12c2[p] = pk2(m12[0], m12[1]);
                rdenp[p]  = pk2(rd[0], rd[1]);
            }
        }

        // pass 2: X field, scalar FFMA-imm conv (rt=1, no pack movs / const regs)
        {
            float accX[8] = {0,0,0,0,0,0,0,0};
            #pragma unroll
            for (int j = 0; j < 18; j++) {
                const float vX = hX[(yb + j)*HXX + x];
                #pragma unroll
                for (int r = 0; r < 8; r++) {
                    const int k = j - r;
                    if (k >= 0 && k < 11)
                        accX[r] = fmaf(Gw(k), vX, accX[r]);
                }
            }
            // whole-thread validity: last y-tile's invalid rows are full 8-row groups
            if (ty0 + yb < IMG_H) {
                #pragma unroll
                for (int p = 0; p < 4; p++) {
                    tsum = fmaf(accX[2*p+0] + lo2(mu12c2[p]), lo2(rdenp[p]), tsum);
                    tsum = fmaf(accX[2*p+1] + hi2(mu12c2[p]), hi2(rdenp[p]), tsum);
                }
            }
        }
    }

    // ---------- block reduction ----------
    #pragma unroll
    for (int o = 16; o; o >>= 1) tsum += __shfl_down_sync(0xFFFFFFFFu, tsum, o);
    __shared__ float wsum[12];
    __shared__ bool is_last;
    if ((tid & 31) == 0) wsum[tid >> 5] = tsum;
    __syncthreads();
    if (tid == 0) {
        float s = 0.f;
        #pragma unroll
        for (int i = 0; i < 12; i++) s += wsum[i];
        g_blocksums[(blockIdx.z * GRID_Y + blockIdx.y) * GRID_X + blockIdx.x] = s;
        __threadfence();
        unsigned t = atomicAdd(&g_count, 1u);
        is_last = (t == NBLK - 1);
    }
    __syncthreads();

    // ---------- last CTA: deterministic final reduction ----------
    if (is_last) {
        __threadfence();
        const float4* src = (const float4*)g_blocksums;
        float s = 0.f;
        for (int i = tid; i < NBLK/4; i += NTHREADS) {
            float4 v = src[i];
            s += (v.x + v.y) + (v.z + v.w);
        }
        #pragma unroll
        for (int o = 16; o; o >>= 1) s += __shfl_down_sync(0xFFFFFFFFu, s, o);
        if ((tid & 31) == 0) wsum[tid >> 5] = s;
        __syncthreads();
        if (tid == 0) {
            float tot = 0.f;
            #pragma unroll
            for (int i = 0; i < 12; i++) tot += wsum[i];
            out[0] = tot / NPIX;
            g_count = 0;                      // reset for next replay
        }
    }
}

extern "C" void kernel_launch(void* const* d_in, const int* in_sizes, int n_in,
                              void* d_out, int out_size)
{
    const float* img1 = (const float*)d_in[0];
    const float* img2 = (const float*)d_in[1];
    float* out = (float*)d_out;

    cudaFuncSetAttribute(ssim_kernel,
                         cudaFuncAttributeMaxDynamicSharedMemorySize, SMEM_BYTES);

    dim3 grid(GRID_X, GRID_Y, NCH);
    ssim_kernel<<<grid, NTHREADS, SMEM_BYTES>>>(img1, img2, out);
}